// round 3
// baseline (speedup 1.0000x reference)
#include <cuda_runtime.h>
#include <cuda_bf16.h>
#include <math.h>

// Problem constants (fixed by setup_inputs): B=32, N=M=1024, F=4
#define BB    32
#define NN    1024
#define MM    1024
#define LL    (NN + MM - 1)    // 2047
#define BT    256              // block threads
#define FT    128              // forward threads
#define RR    8                // rows per forward thread
#define FW    4                // forward warps
#define STEPS (MM + FT - 1)    // 1151
#define RQ    64               // ring slots per warp boundary

// backtrack window: WIN_I rows (i) x WIN_J cols (j)
#define WIN_I 80
#define WIN_J 64

// Move matrix, column-major per batch: moves[b][j][i]. Padded for window over-read.
__device__ __align__(16) unsigned char g_moves[(size_t)BB * NN * MM + 256];
__device__ float g_loss[BB];

__device__ __forceinline__ float fsqrt_approx(float x) {
    float r;
    asm("sqrt.approx.f32 %0, %1;" : "=f"(r) : "f"(x));
    return r;
}

// 16B atomic ring ops (tag travels with data in one shared transaction)
__device__ __forceinline__ void ring_push(unsigned addr, float a, float b, int tag) {
    asm volatile("st.volatile.shared.v4.b32 [%0], {%1,%2,%3,%4};"
                 :: "r"(addr), "r"(__float_as_int(a)), "r"(__float_as_int(b)),
                    "r"(tag), "r"(0) : "memory");
}
__device__ __forceinline__ void ring_wait(unsigned addr, int tag, float& a, float& b) {
    int x, y, z, w;
    while (true) {
        asm volatile("ld.volatile.shared.v4.b32 {%0,%1,%2,%3}, [%4];"
                     : "=r"(x), "=r"(y), "=r"(z), "=r"(w) : "r"(addr));
        if (z == tag) break;
    }
    a = __int_as_float(x);
    b = __int_as_float(y);
}
__device__ __forceinline__ void prog_store(unsigned addr, int v) {
    asm volatile("st.volatile.shared.b32 [%0], %1;" :: "r"(addr), "r"(v) : "memory");
}
__device__ __forceinline__ int prog_load(unsigned addr) {
    int v;
    asm volatile("ld.volatile.shared.b32 %0, [%1];" : "=r"(v) : "r"(addr));
    return v;
}

__global__ __launch_bounds__(BT, 1)
void dtw_fused(const float* __restrict__ preds, const float* __restrict__ targs,
               const float* __restrict__ subcoef)
{
    const int b   = blockIdx.x;
    const int tid = threadIdx.x;

    __shared__ float2 txy[MM];                         // 8 KB target basis coords
    __shared__ __align__(16) float4 ring[FW][RQ];      // 4 KB warp-boundary rings
    __shared__ int progress[FW];
    __shared__ unsigned int path[LL];                  // 8 KB packed (i<<16|j)
    __shared__ __align__(16) unsigned char win [WIN_J * WIN_I];  // 5 KB moves window
    __shared__ __align__(16) unsigned char win2[WIN_J * WIN_I];  // 5 KB 2-step jump table
    __shared__ int s_i, s_j, s_cnt, s_done;
    __shared__ float warp_sums[BT / 32];

    const float* pb = preds + (size_t)b * NN * 4;
    const float* tb = targs + (size_t)b * MM * 4;
    const float INF = __int_as_float(0x7f800000);

    // ---- init smem ----
    for (int idx = tid; idx < MM; idx += BT) {
        const float2 tv = *(const float2*)(tb + (size_t)idx * 4);
        txy[idx] = tv;
    }
    {   // ring tags = -1  (4 warps x 64 slots = 256 = BT)
        float4* rf = &ring[0][0];
        rf[tid] = make_float4(0.0f, 0.0f, __int_as_float(-1), 0.0f);
    }
    if (tid < FW) progress[tid] = 0;
    __syncthreads();

    // =====================================================================
    // Forward DP: 4 decoupled warps, thread t owns rows 8t..8t+7.
    // At step s thread t computes column c = s - t. No block barriers:
    // warp boundaries handoff through ring buffers (16B atomic slots).
    // =====================================================================
    if (tid < FT) {
        const int t    = tid;
        const int lane = t & 31;
        const int warp = t >> 5;

        float px[RR], py[RR], left[RR];
        #pragma unroll
        for (int q = 0; q < RR; ++q) {
            const int idx = t * RR + q;
            const float2 pv = *(const float2*)(pb + (size_t)idx * 4);
            px[q] = pv.x; py[q] = pv.y;
            left[q] = INF;
        }
        float last1 = INF;   // D[8t+7][c-1]
        float last2 = INF;   // D[8t+7][c-2]

        const unsigned ring_base = (unsigned)__cvta_generic_to_shared(&ring[0][0]);
        const unsigned ring_self = ring_base + warp * (RQ * 16);
        const unsigned ring_prev = ring_self - (RQ * 16);
        const unsigned prog_base = (unsigned)__cvta_generic_to_shared(progress);
        const unsigned prog_self = prog_base + warp * 4;
        const unsigned prog_next = prog_base + (warp + 1) * 4;
        int prog_cached = 0;

        unsigned char* mb = g_moves + ((size_t)b << 20) + t * RR;

        for (int s = 0; s < STEPS; ++s) {
            float up0 = __shfl_up_sync(0xffffffffu, last1, 1);
            float dg0 = __shfl_up_sync(0xffffffffu, last2, 1);
            if (lane == 0) {
                if (warp == 0) { up0 = INF; dg0 = INF; }
                else {
                    ring_wait(ring_prev + (((s - 1) & (RQ - 1)) << 4), s - 1, up0, dg0);
                    if ((s & 15) == 0) prog_store(prog_self, s);
                }
            }

            const int c = s - t;
            if ((unsigned)c < (unsigned)MM) {
                const float2 tj = txy[c];
                float up = up0, dg = dg0;
                unsigned mw0 = 0, mw1 = 0;
                #pragma unroll
                for (int q = 0; q < RR; ++q) {
                    const float lf = left[q];
                    float best = fminf(fminf(up, dg), lf);
                    // argmin over [dg, up, lf], first-minimum tie-break (jnp.argmin)
                    int m = 0; float bm = dg;
                    if (up < bm) { bm = up; m = 1; }
                    if (lf < bm) { m = 2; }
                    if (q == 0) best = (best == INF) ? 0.0f : best;  // (0,0) seed only
                    const float dx = px[q] - tj.x;
                    const float dy = py[q] - tj.y;
                    const float cur = fsqrt_approx(fmaf(dx, dx, dy * dy)) + best;
                    dg = lf;
                    left[q] = cur;
                    up = cur;
                    if (q < 4) mw0 |= (unsigned)m << (8 * q);
                    else       mw1 |= (unsigned)m << (8 * (q - 4));
                }
                *(uint2*)(mb + ((size_t)c << 10)) = make_uint2(mw0, mw1);
                last2 = last1;
                last1 = left[RR - 1];
            }

            if (lane == 31 && warp < FW - 1) {
                if (prog_cached < s - 47) {
                    do { prog_cached = prog_load(prog_next); } while (prog_cached < s - 47);
                }
                ring_push(ring_self + ((s & (RQ - 1)) << 4), last1, last2, s);
            }
        }
    }
    __syncthreads();

    // =====================================================================
    // Backtrack: block-cooperative windows + jump-2 table, thread 0 walks
    // 2 steps per shared load.
    // =====================================================================
    if (tid == 0) {
        s_i = NN - 1; s_j = MM - 1; s_cnt = 1; s_done = 0;
        path[0] = ((unsigned)(NN - 1) << 16) | (unsigned)(MM - 1);
    }
    const unsigned char* mvb = g_moves + ((size_t)b << 20);

    for (;;) {
        __syncthreads();                       // publishes s_* from walker
        if (s_done) break;
        const int ci  = s_i, cj = s_j;
        const int ilo = max(ci - 48, 0) & ~15; // i - ilo in [48, 63] (or < when near 0)
        const int jlo = max(cj - (WIN_J - 1), 0);

        // load window: WIN_J cols x WIN_I bytes, uint4 chunks (320 tasks)
        for (int task = tid; task < WIN_J * (WIN_I / 16); task += BT) {
            const int jo = task / (WIN_I / 16);
            const int q  = task % (WIN_I / 16);
            const uint4 v = *(const uint4*)(mvb + (((size_t)(jlo + jo)) << 10) + ilo + q * 16);
            *(uint4*)&win[jo * WIN_I + q * 16] = v;
        }
        __syncthreads();

        // build jump-2 table: byte = m1 | m2<<2 (m2==3 -> second step leaves window)
        for (int cidx = tid; cidx < WIN_J * WIN_I; cidx += BT) {
            const int jo = cidx / WIN_I;
            const int io = cidx % WIN_I;
            const int m1 = win[cidx] & 3;
            const int io2 = io - (m1 != 2);
            const int jo2 = jo - (m1 != 1);
            int m2 = 3;
            if ((io2 | jo2) >= 0) m2 = win[jo2 * WIN_I + io2] & 3;
            win2[cidx] = (unsigned char)(m1 | (m2 << 2));
        }
        __syncthreads();

        if (tid == 0) {
            int i = ci, j = cj, cnt = s_cnt, done = 0;
            int io = i - ilo, jo = j - jlo;
            int a = jo * WIN_I + io;
            while ((io | jo) >= 0) {
                const int cm = win2[a];
                const int m1 = cm & 3;
                int di = (m1 != 2), dj = (m1 != 1);
                i -= di; j -= dj; io -= di; jo -= dj; a -= di + dj * WIN_I;
                path[cnt++] = ((unsigned)i << 16) | (unsigned)j;
                if ((i | j) == 0) { done = 1; break; }
                const int m2 = cm >> 2;
                if (m2 == 3) break;
                di = (m2 != 2); dj = (m2 != 1);
                i -= di; j -= dj; io -= di; jo -= dj; a -= di + dj * WIN_I;
                path[cnt++] = ((unsigned)i << 16) | (unsigned)j;
                if ((i | j) == 0) { done = 1; break; }
            }
            s_i = i; s_j = j; s_cnt = cnt; s_done = done;
        }
    }

    // ---- path loss, 256 threads ----
    const float c0 = subcoef[0];
    const float c1 = subcoef[1];
    const int  len = s_cnt;

    float acc = 0.0f;
    for (int p = tid; p < len; p += BT) {
        const unsigned pk = path[p];
        const int ai = (int)(pk >> 16);
        const int bj = (int)(pk & 0xffffu);
        const float2 pp = *(const float2*)(pb + (size_t)ai * 4);
        const float2 tv = *(const float2*)(tb + (size_t)bj * 4);
        acc += fabsf(pp.x - tv.x) * c0 + fabsf(pp.y - tv.y) * c1;
    }
    #pragma unroll
    for (int off = 16; off > 0; off >>= 1)
        acc += __shfl_down_sync(0xffffffffu, acc, off);
    if ((tid & 31) == 0) warp_sums[tid >> 5] = acc;
    __syncthreads();
    if (tid == 0) {
        float tot = 0.0f;
        #pragma unroll
        for (int w = 0; w < BT / 32; ++w) tot += warp_sums[w];
        g_loss[b] = tot;
    }
}

// Deterministic fixed-order final sum
__global__ void dtw_finalize(float* __restrict__ out)
{
    float tot = 0.0f;
    #pragma unroll
    for (int b = 0; b < BB; ++b) tot += g_loss[b];
    out[0] = tot;
}

extern "C" void kernel_launch(void* const* d_in, const int* in_sizes, int n_in,
                              void* d_out, int out_size)
{
    const float* preds   = (const float*)d_in[0];
    const float* targs   = (const float*)d_in[1];
    const float* subcoef = (const float*)d_in[2];
    float* out = (float*)d_out;

    dtw_fused   <<<BB, BT>>>(preds, targs, subcoef);
    dtw_finalize<<<1, 1>>>(out);
}

// round 6
// speedup vs baseline: 4.4970x; 4.4970x over previous
#include <cuda_runtime.h>
#include <cuda_bf16.h>
#include <math.h>

// Problem constants (fixed by setup_inputs): B=32, N=M=1024, F=4
#define BB    32
#define NN    1024
#define MM    1024
#define LL    (NN + MM - 1)   // 2047
#define BT    128             // block threads
#define RR    8               // rows per thread (128*8 = 1024)
#define NG    (MM / 2)        // 512 column groups (2 cols per group)
#define STEPS (NG + BT - 1)   // 639
#define NWARP (BT / 32)       // 4

// Move matrix, column-major per batch: moves[b][j][i], enc = di | dj<<1.
// Padded for backtrack window over-read.
__device__ __align__(16) unsigned char g_moves[(size_t)BB * NN * MM + 256];
__device__ float g_loss[BB];
__device__ int   g_done;     // zero-init; self-resetting each launch

__device__ __forceinline__ float fsqrt_approx(float x) {
    float r;
    asm("sqrt.approx.f32 %0, %1;" : "=f"(r) : "f"(x));
    return r;
}

__global__ __launch_bounds__(BT, 1)
void dtw_fused(const float* __restrict__ preds, const float* __restrict__ targs,
               const float* __restrict__ subcoef, float* __restrict__ out)
{
    const int b    = blockIdx.x;
    const int tid  = threadIdx.x;
    const int lane = tid & 31;
    const int warp = tid >> 5;

    __shared__ float2 txy[MM];                           // 8 KB target basis
    __shared__ float4 sb[2][NWARP];                      // warp-boundary handoff
    __shared__ unsigned int path[LL];                    // 8 KB packed (i<<16|j)
    __shared__ __align__(16) unsigned char win[32][48];  // backtrack window
    __shared__ int s_i, s_j, s_cnt;
    __shared__ float warp_sums[NWARP];

    const float* pb = preds + (size_t)b * NN * 4;
    const float* tb = targs + (size_t)b * MM * 4;
    const float INF = __int_as_float(0x7f800000);

    // ---- init ----
    for (int idx = tid; idx < MM; idx += BT)
        txy[idx] = *(const float2*)(tb + (size_t)idx * 4);
    if (tid < 2 * NWARP)
        ((float4*)sb)[tid] = make_float4(INF, INF, INF, 0.0f);

    float px[RR], py[RR], left[RR];
    #pragma unroll
    for (int q = 0; q < RR; ++q) {
        const float2 pv = *(const float2*)(pb + (size_t)(tid * RR + q) * 4);
        px[q] = pv.x; py[q] = pv.y;
        left[q] = INF;
    }
    __syncthreads();

    // =====================================================================
    // Forward DP: thread t owns rows 8t..8t+7; at step s it processes
    // column group g = s - t (columns 2g, 2g+1). Handoff to the next thread:
    // bot0/bot1 = bottom-row D at cols 2g, 2g+1 (this step), pb1 = bottom at
    // col 2g-1 (previous step). In-warp via 3 shfls, warp boundary via a
    // double-buffered float4 smem slot. One barrier per step.
    // =====================================================================
    float bot0 = INF, bot1 = INF, pb1 = INF;
    unsigned char* mb = g_moves + ((size_t)b << 20) + tid * RR;

    for (int s = 0; s < STEPS; ++s) {
        float nb0 = __shfl_up_sync(0xffffffffu, bot0, 1);
        float nb1 = __shfl_up_sync(0xffffffffu, bot1, 1);
        float nbp = __shfl_up_sync(0xffffffffu, pb1, 1);
        if (lane == 0) {
            if (warp == 0) { nb0 = INF; nb1 = INF; nbp = INF; }
            else {
                const float4 v = sb[(s + 1) & 1][warp - 1];  // producer step s-1
                nb0 = v.x; nb1 = v.y; nbp = v.z;
            }
        }

        const int g = s - tid;
        if ((unsigned)g < (unsigned)NG) {
            const int c0 = g * 2;
            const float2 t0 = txy[c0];
            const float2 t1 = txy[c0 + 1];

            // costs: independent of DP values (off critical chain)
            float cst0[RR], cst1[RR];
            #pragma unroll
            for (int q = 0; q < RR; ++q) {
                const float dx0 = px[q] - t0.x, dy0 = py[q] - t0.y;
                cst0[q] = fsqrt_approx(fmaf(dx0, dx0, dy0 * dy0));
                const float dx1 = px[q] - t1.x, dy1 = py[q] - t1.y;
                cst1[q] = fsqrt_approx(fmaf(dx1, dx1, dy1 * dy1));
            }

            pb1 = bot1;   // becomes "bottom at c0-1" for next step's handoff

            // ---- column c0 ----
            float up0 = nb0, dg0 = nbp;
            float cur0[RR];
            unsigned wa0 = 0, wa1 = 0;   // move bytes rows 0-3 / 4-7, col c0
            #pragma unroll
            for (int q = 0; q < RR; ++q) {
                const float lf = left[q];
                const float pm = fminf(dg0, lf);      // off-chain for q>0
                float best = fminf(up0, pm);
                if (q == 0) best = (best == INF) ? 0.0f : best;  // (0,0) seed only
                // first-min argmin over [dg, up, lf] -> enc = di | dj<<1
                float bm = dg0; int enc = 3;           // diag: di=1,dj=1
                if (up0 < bm) { bm = up0; enc = 1; }   // up:   di=1,dj=0
                if (lf  < bm) { enc = 2; }             // left: di=0,dj=1
                const float cur = best + cst0[q];
                dg0 = lf;
                up0 = cur;
                cur0[q] = cur;
                if (q < 4) wa0 |= (unsigned)enc << (8 * q);
                else       wa1 |= (unsigned)enc << (8 * (q - 4));
            }

            // ---- column c0+1 ----
            float up1 = nb1, dg1 = nb0;
            unsigned wb0 = 0, wb1 = 0;
            #pragma unroll
            for (int q = 0; q < RR; ++q) {
                const float lf = cur0[q];
                const float pm = fminf(dg1, lf);
                const float best = fminf(up1, pm);
                float bm = dg1; int enc = 3;
                if (up1 < bm) { bm = up1; enc = 1; }
                if (lf  < bm) { enc = 2; }
                const float cur = best + cst1[q];
                dg1 = lf;
                up1 = cur;
                left[q] = cur;                         // left for next group
                if (q < 4) wb0 |= (unsigned)enc << (8 * q);
                else       wb1 |= (unsigned)enc << (8 * (q - 4));
            }

            bot0 = cur0[RR - 1];
            bot1 = left[RR - 1];

            *(uint2*)(mb + ((size_t)c0 << 10))       = make_uint2(wa0, wa1);
            *(uint2*)(mb + ((size_t)(c0 + 1) << 10)) = make_uint2(wb0, wb1);
        }

        if (lane == 31)
            sb[s & 1][warp] = make_float4(bot0, bot1, pb1, 0.0f);
        __syncthreads();
    }

    // =====================================================================
    // Backtrack: warp-0 windowed walk (48 rows x 32 cols per window).
    // enc bits: i -= enc&1, j -= (enc>>1)&1.
    // =====================================================================
    if (tid < 32) {
        const unsigned char* mvb = g_moves + ((size_t)b << 20);
        int i = NN - 1, j = MM - 1, cnt = 1;
        if (tid == 0) path[0] = ((unsigned)i << 16) | (unsigned)j;

        while (i | j) {
            const int ilo = max(i - 31, 0) & ~15;   // 16B-aligned; i-ilo in [31,46]
            const int jlo = max(j - 31, 0);

            {   // load 48 rows x 32 cols; lane takes column jlo+lane
                const unsigned char* src = mvb + (((size_t)(jlo + tid)) << 10) + ilo;
                *(uint4*)&win[tid][0]  = *(const uint4*)(src);
                *(uint4*)&win[tid][16] = *(const uint4*)(src + 16);
                *(uint4*)&win[tid][32] = *(const uint4*)(src + 32);
            }
            __syncwarp();

            if (tid == 0) {
                while ((i >= ilo) && (j >= jlo) && (i | j)) {
                    const unsigned m = win[j - jlo][i - ilo];
                    i -= (int)(m & 1u);
                    j -= (int)((m >> 1) & 1u);
                    path[cnt++] = ((unsigned)i << 16) | (unsigned)j;
                }
                s_i = i; s_j = j; s_cnt = cnt;
            }
            __syncwarp();
            i = s_i; j = s_j; cnt = s_cnt;
        }
        if (tid == 0) s_cnt = cnt;
    }
    __syncthreads();

    // ---- path loss ----
    const float c0 = subcoef[0];
    const float c1 = subcoef[1];
    const int  len = s_cnt;

    float acc = 0.0f;
    for (int p = tid; p < len; p += BT) {
        const unsigned pk = path[p];
        const int ai = (int)(pk >> 16);
        const int bj = (int)(pk & 0xffffu);
        const float2 pp = *(const float2*)(pb + (size_t)ai * 4);
        const float2 tv = *(const float2*)(tb + (size_t)bj * 4);
        acc += fabsf(pp.x - tv.x) * c0 + fabsf(pp.y - tv.y) * c1;
    }
    #pragma unroll
    for (int off = 16; off > 0; off >>= 1)
        acc += __shfl_down_sync(0xffffffffu, acc, off);
    if (lane == 0) warp_sums[warp] = acc;
    __syncthreads();

    // ---- last-CTA deterministic finalize (fixed-order sum) ----
    if (tid == 0) {
        float tot = 0.0f;
        #pragma unroll
        for (int w = 0; w < NWARP; ++w) tot += warp_sums[w];
        g_loss[b] = tot;
        __threadfence();
        const int old = atomicAdd(&g_done, 1);
        if (old == BB - 1) {
            __threadfence();
            float t2 = 0.0f;
            #pragma unroll
            for (int x = 0; x < BB; ++x) t2 += g_loss[x];
            out[0] = t2;
            g_done = 0;   // self-reset for next graph replay
        }
    }
}

extern "C" void kernel_launch(void* const* d_in, const int* in_sizes, int n_in,
                              void* d_out, int out_size)
{
    const float* preds   = (const float*)d_in[0];
    const float* targs   = (const float*)d_in[1];
    const float* subcoef = (const float*)d_in[2];
    float* out = (float*)d_out;

    dtw_fused<<<BB, BT>>>(preds, targs, subcoef, out);
}